// round 17
// baseline (speedup 1.0000x reference)
#include <cuda_runtime.h>
#include <math.h>

// Problem constants
#define B_    16
#define C_    64
#define H_    224
#define W_    224
#define HW_   (H_ * W_)           // 50176
#define HW4_  (HW_ / 4)           // 12544
#define CHW4_ ((C_ * HW_) / 4)    // 802816
#define ROW4  56                  // float4 per row

#define NQ    4                   // channel quarters
#define QSTRIDE (16 * HW_)        // float stride between psum quarters (802816)

// Device-global scratch (no allocation allowed)
__device__ float4       g_psum4[NQ * B_ * H_ * ROW4];  // 12.8 MB per-quarter sums
__device__ unsigned int g_maxu[B_ * HW_];              // 3.2 MB flipped-uint channel max
__device__ float        g_gate[B_ * HW_];              // 3.2 MB gates
__device__ unsigned int g_featcnt[B_ * H_];            // per-row partials-done counter
__device__ unsigned int g_gatecnt[B_ * H_];            // per-row gates-done counter

// Monotone float<->uint mapping so atomicMax(uint) == float max; memset-0 valid
// init (all real keys > 0).
__device__ __forceinline__ unsigned int fflip(float f) {
    unsigned int u = __float_as_uint(f);
    return u ^ ((unsigned int)(((int)u) >> 31) | 0x80000000u);
}
__device__ __forceinline__ float funflip(unsigned int k) {
    unsigned int x = 0x80000000u | ~(unsigned int)(((int)k) >> 31);
    return __uint_as_float(k ^ x);
}

// ---------------------------------------------------------------------------
// Single-pass kernel. CTA = (quarter q, row h, batch b); 224 threads.
// Thread (s=t/56, p=t%56) caches 4 channels (q*16+s*4+k) of its row position
// in registers. Phases: partial reduce -> publish -> wait rows h+-3 ->
// halo+conv (56-col slice) -> gate exchange -> multiply cached x, store.
// x touches DRAM exactly once each way.
// ---------------------------------------------------------------------------
__global__ void __launch_bounds__(224, 7) fused_single_pass(
        const float* __restrict__ x,
        const float* __restrict__ conv_w,
        const float* __restrict__ conv_b,
        float* __restrict__ out) {
    __shared__ float4 scr_s[NQ][ROW4];     // 3.5 KB  per-slice sums
    __shared__ float4 scr_m[NQ][ROW4];     // 3.5 KB  per-slice maxes
    __shared__ float  s_halo[2][7][64];    // 3.5 KB  conv halo (62 cols used)
    __shared__ float  s_w[98];

    int t = threadIdx.x;                   // 0..223
    int q = blockIdx.x;                    // 0..3 channel quarter
    int h = blockIdx.y;                    // 0..223
    int b = blockIdx.z;                    // 0..15
    int s = t / ROW4;                      // 0..3 (4-channel slice)
    int p = t - s * ROW4;                  // 0..55 (float4 position)

    // Conv weights; fold mean's 1/64 into the avg-channel taps.
    if (t < 98) {
        float wv = conv_w[t];
        s_w[t] = (t < 49) ? wv * (1.0f / 64.0f) : wv;
    }

    // ---- P1: load 4 channels into registers (DRAM, once) ----
    const float4* x4 = (const float4*)x;
    long xbase = (long)b * CHW4_ + (long)(q * 16 + s * 4) * HW4_ + h * ROW4 + p;
    float4 v0 = __ldcs(x4 + xbase + 0L * HW4_);
    float4 v1 = __ldcs(x4 + xbase + 1L * HW4_);
    float4 v2 = __ldcs(x4 + xbase + 2L * HW4_);
    float4 v3 = __ldcs(x4 + xbase + 3L * HW4_);

    float4 fs, fm;
    fs.x = v0.x + v1.x + v2.x + v3.x;  fs.y = v0.y + v1.y + v2.y + v3.y;
    fs.z = v0.z + v1.z + v2.z + v3.z;  fs.w = v0.w + v1.w + v2.w + v3.w;
    fm.x = fmaxf(fmaxf(v0.x, v1.x), fmaxf(v2.x, v3.x));
    fm.y = fmaxf(fmaxf(v0.y, v1.y), fmaxf(v2.y, v3.y));
    fm.z = fmaxf(fmaxf(v0.z, v1.z), fmaxf(v2.z, v3.z));
    fm.w = fmaxf(fmaxf(v0.w, v1.w), fmaxf(v2.w, v3.w));
    scr_s[s][p] = fs;
    scr_m[s][p] = fm;
    __syncthreads();

    // ---- P2: combine 4 slices -> 16-ch partials; publish ----
    int rowid = b * H_ + h;
    if (t < ROW4) {
        float4 a = scr_s[0][t], m = scr_m[0][t];
#pragma unroll
        for (int j = 1; j < NQ; j++) {
            float4 a2 = scr_s[j][t], m2 = scr_m[j][t];
            a.x += a2.x; a.y += a2.y; a.z += a2.z; a.w += a2.w;
            m.x = fmaxf(m.x, m2.x); m.y = fmaxf(m.y, m2.y);
            m.z = fmaxf(m.z, m2.z); m.w = fmaxf(m.w, m2.w);
        }
        g_psum4[((q * B_ + b) * H_ + h) * ROW4 + t] = a;      // deterministic slot
        unsigned int* mrow = g_maxu + rowid * W_ + 4 * t;
        atomicMax(mrow + 0, fflip(m.x));                       // order-independent
        atomicMax(mrow + 1, fflip(m.y));
        atomicMax(mrow + 2, fflip(m.z));
        atomicMax(mrow + 3, fflip(m.w));
    }
    __syncthreads();
    if (t == 0) {
        __threadfence();
        atomicAdd(&g_featcnt[rowid], 1u);
    }

    // ---- P3: wait for rows h-3..h+3 feat partials ----
    if (t < 7) {
        int hh = h - 3 + t;
        if (hh >= 0 && hh < H_) {
            volatile unsigned int* f = &g_featcnt[b * H_ + hh];
            while (*f < (unsigned int)NQ) __nanosleep(200);
            __threadfence();               // acquire
        }
    }
    __syncthreads();

    // ---- P4: halo (7 rows x 62 cols x 2 ch) for this CTA's 56-col slice ----
    for (int i = t; i < 2 * 7 * 62; i += 224) {
        int ch = i / 434;
        int rr = i - ch * 434;
        int r  = rr / 62;
        int cc = rr - r * 62;
        int gh = h - 3 + r;
        int gw = 56 * q - 3 + cc;
        float val = 0.f;
        if (gh >= 0 && gh < H_ && gw >= 0 && gw < W_) {
            if (ch == 0) {                 // sum of 4 partials, fixed order
                const float* ps = (const float*)g_psum4;
                int e = ((b * H_ + gh) * W_) + gw;
                val = ps[e] + ps[e + QSTRIDE] + ps[e + 2 * QSTRIDE]
                    + ps[e + 3 * QSTRIDE];
            } else {
                val = funflip(g_maxu[(b * H_ + gh) * W_ + gw]);
            }
        }
        s_halo[ch][r][cc] = val;
    }
    __syncthreads();

    // ---- P5: conv 7x7 + sigmoid for cols [56q, 56q+56) ----
    if (t < 56) {
        float acc = conv_b[0];
#pragma unroll
        for (int ch = 0; ch < 2; ch++)
#pragma unroll
            for (int kh = 0; kh < 7; kh++) {
                const float* rp = &s_halo[ch][kh][t];
                const float* wk = s_w + ch * 49 + kh * 7;
#pragma unroll
                for (int kw = 0; kw < 7; kw++)
                    acc = fmaf(rp[kw], wk[kw], acc);
            }
        g_gate[rowid * W_ + 56 * q + t] = 1.0f / (1.0f + __expf(-acc));
    }
    __syncthreads();
    if (t == 0) {
        __threadfence();
        atomicAdd(&g_gatecnt[rowid], 1u);
    }

    // ---- P5b: wait for full gate row ----
    if (t == 0) {
        volatile unsigned int* f = &g_gatecnt[rowid];
        while (*f < (unsigned int)NQ) __nanosleep(200);
        __threadfence();                   // acquire
    }
    __syncthreads();

    // ---- P6: multiply cached x by gates, stream out ----
    float4 g4 = ((const float4*)g_gate)[rowid * ROW4 + p];
    float4* o4 = (float4*)out;
    v0.x *= g4.x; v0.y *= g4.y; v0.z *= g4.z; v0.w *= g4.w; __stcs(o4 + xbase + 0L * HW4_, v0);
    v1.x *= g4.x; v1.y *= g4.y; v1.z *= g4.z; v1.w *= g4.w; __stcs(o4 + xbase + 1L * HW4_, v1);
    v2.x *= g4.x; v2.y *= g4.y; v2.z *= g4.z; v2.w *= g4.w; __stcs(o4 + xbase + 2L * HW4_, v2);
    v3.x *= g4.x; v3.y *= g4.y; v3.z *= g4.z; v3.w *= g4.w; __stcs(o4 + xbase + 3L * HW4_, v3);
}

// ---------------------------------------------------------------------------
extern "C" void kernel_launch(void* const* d_in, const int* in_sizes, int n_in,
                              void* d_out, int out_size) {
    const float* x      = (const float*)d_in[0];
    const float* conv_w = (const float*)d_in[1];
    const float* conv_b = (const float*)d_in[2];
    float* out = (float*)d_out;

    // Reset accumulators/counters (device globals persist across replays).
    void* pm = nullptr; void* pf = nullptr; void* pg = nullptr;
    cudaGetSymbolAddress(&pm, g_maxu);
    cudaGetSymbolAddress(&pf, g_featcnt);
    cudaGetSymbolAddress(&pg, g_gatecnt);
    cudaMemsetAsync(pm, 0, (size_t)B_ * HW_ * sizeof(unsigned int));  // 3.2 MB
    cudaMemsetAsync(pf, 0, (size_t)B_ * H_ * sizeof(unsigned int));
    cudaMemsetAsync(pg, 0, (size_t)B_ * H_ * sizeof(unsigned int));

    // Single pass over x: 4 quarters x 224 rows x 16 batches = 14336 CTAs.
    dim3 grd(NQ, H_, B_);
    fused_single_pass<<<grd, 224>>>(x, conv_w, conv_b, out);
}